// round 15
// baseline (speedup 1.0000x reference)
#include <cuda_runtime.h>
#include <cuda_fp16.h>
#include <math.h>

typedef unsigned int u32;

// ---------------- static device scratch (allocation-free rule) ----------------
__device__ __half g_xh[48*48*320];            // L1 input NHWC fp16
__device__ __half g_h0[96*96*192];            // L1 out / L2 in
__device__ __half g_h1[192*192*192];          // L2 out / L3 in
__device__ __half g_h2[384*384*192];          // L3 out / L4 in
// B weight BLOBS: [z][chunk][tap9] x (NTILE rows x 32B), consumption order
__device__ __align__(256) __half g_wb1[12*20*9*64*16];
__device__ __align__(256) __half g_wb2[12*12*9*64*16];
__device__ __align__(256) __half g_wb3[12*12*9*64*16];
__device__ __align__(256) __half g_wb4[12*9*16*16];
__device__ float g_b1q[192];
__device__ float g_b2q[192];
__device__ float g_b3q[192];
__device__ float g_b4q[3];
__device__ float g_params[24];

// ---------------- PTX wrappers ----------------
#define CPASYNC(dst, src, sz) \
    asm volatile("cp.async.cg.shared.global [%0], [%1], 16, %2;" :: "r"(dst), "l"(src), "r"(sz))
#define CPCOMMIT() asm volatile("cp.async.commit_group;")
#define CPWAIT(n)  asm volatile("cp.async.wait_group %0;" :: "n"(n))
#define LDSM4(r0,r1,r2,r3,addr) \
    asm volatile("ldmatrix.sync.aligned.m8n8.x4.shared.b16 {%0,%1,%2,%3}, [%4];" \
        : "=r"(r0),"=r"(r1),"=r"(r2),"=r"(r3) : "r"(addr))
#define MMA16816(c0,c1,c2,c3,a0,a1,a2,a3,b0,b1) \
    asm volatile("mma.sync.aligned.m16n8k16.row.col.f32.f16.f16.f32 " \
        "{%0,%1,%2,%3}, {%4,%5,%6,%7}, {%8,%9}, {%0,%1,%2,%3};" \
        : "+f"(c0),"+f"(c1),"+f"(c2),"+f"(c3) \
        : "r"(a0),"r"(a1),"r"(a2),"r"(a3),"r"(b0),"r"(b1))
#define MBAR_INIT(mb, cnt) \
    asm volatile("mbarrier.init.shared.b64 [%0], %1;" :: "r"(mb), "r"(cnt) : "memory")
#define MBAR_ARRIVE(mb) \
    asm volatile("mbarrier.arrive.shared.b64 _, [%0];" :: "r"(mb) : "memory")
#define MBAR_EXPECT_TX(mb, bytes) \
    asm volatile("mbarrier.arrive.expect_tx.shared.b64 _, [%0], %1;" :: "r"(mb), "r"(bytes) : "memory")
#define TMA_BULK(dst, src, bytes, mb) \
    asm volatile("cp.async.bulk.shared::cluster.global.mbarrier::complete_tx::bytes [%0], [%1], %2, [%3];" \
        :: "r"(dst), "l"(src), "r"(bytes), "r"(mb) : "memory")
#define MBAR_WAIT(mb, parity) do { \
    u32 _done = 0; \
    while (!_done) { \
        asm volatile("{\n\t.reg .pred p;\n\t" \
            "mbarrier.try_wait.parity.acquire.cta.shared::cta.b64 p, [%1], %2;\n\t" \
            "selp.b32 %0, 1, 0, p;\n\t}" \
            : "=r"(_done) : "r"(mb), "r"(parity) : "memory"); \
    } \
} while(0)

// ---------------- small prep kernels ----------------
__global__ void quant_scalars(const float* __restrict__ b1, const float* __restrict__ b2,
                              const float* __restrict__ b3, const float* __restrict__ b4,
                              const float* __restrict__ relus, const int* __restrict__ dvds,
                              const int* __restrict__ bitsp) {
    int i = threadIdx.x;
    if (i < 192) {
        g_b1q[i] = rintf(b1[i]);
        g_b2q[i] = rintf(b2[i]);
        g_b3q[i] = rintf(b3[i]);
    }
    if (i < 3) g_b4q[i] = rintf(b4[i]);
    if (i == 224) {
        float B = bitsp ? (float)(*bitsp) : 8.0f;
        float maxv = exp2f(B) - 1.0f;
        const int sks[3] = {3, 4, 3};
        for (int k = 0; k < 3; k++) {
            float dv = (float)dvds[k];
            g_params[k*6+0] = exp2f(dv - 10.0f);
            g_params[k*6+1] = exp2f(9.0f - dv);
            g_params[k*6+2] = rintf((maxv / relus[k]) * 33554432.0f);
            float sk = (float)sks[k];
            g_params[k*6+3] = floorf((relus[k] + exp2f(sk - 1.0f)) * exp2f(-sk));
            g_params[k*6+4] = exp2f(24.0f - sk);
            g_params[k*6+5] = exp2f(sk - 25.0f);
        }
        float dv3 = (float)dvds[3];
        g_params[18] = exp2f(dv3 - 9.0f);
        g_params[19] = exp2f(8.0f - dv3);
    }
}

// NCHW f32 -> NHWC fp16 (values are small ints: exact)
__global__ void nchw2nhwc(const float* __restrict__ src, __half* __restrict__ dst,
                          int C, int HW) {
    int idx = blockIdx.x * blockDim.x + threadIdx.x;
    if (idx >= C * HW) return;
    int s = idx / C, c = idx % C;
    dst[idx] = __float2half_rn(src[c * HW + s]);
}

// Layers 1-3: w [CIN][192][5][5] f32 -> blobs [z=cog*4+p][chunk][tap][64 rows x 16ci].
__global__ void prep_wb3x(const float* __restrict__ w1, const float* __restrict__ w2,
                          const float* __restrict__ w3) {
    __shared__ float tile[320 * 25];
    const int which = blockIdx.y;
    const float* w = which == 0 ? w1 : (which == 1 ? w2 : w3);
    __half* wb     = which == 0 ? g_wb1 : (which == 1 ? g_wb2 : g_wb3);
    const int CIN  = which == 0 ? 320 : 192;
    const int COUT = 192;
    const int co = blockIdx.x;
    const int tid = threadIdx.x;
    for (int i = tid; i < CIN * 25; i += 256) {
        int ci = i / 25, t = i % 25;
        tile[i] = w[((size_t)ci * COUT + co) * 25 + t];
    }
    __syncthreads();
    const int nchk = CIN >> 4;
    const int n = co & 63, cog = co >> 6;
    for (int i = tid; i < 25 * nchk; i += 256) {
        int pt = i / nchk, chunk = i % nchk;
        int p, t;
        if (pt < 9)       { p = 0; t = pt; }
        else if (pt < 15) { p = 1; t = pt - 9; }
        else if (pt < 21) { p = 2; t = pt - 15; }
        else              { p = 3; t = pt - 21; }
        int py = p & 1, px = p >> 1;
        int ndx = px ? 2 : 3;
        int dy = (py ? 0 : -1) + t / ndx;
        int dx = (px ? 0 : -1) + t % ndx;
        int ky = py + 2 - 2 * dy, kx = px + 2 - 2 * dx;
        int z = cog * 4 + p;
        size_t blob = ((size_t)z * nchk + chunk) * 9 + t;
        __half h[16];
        #pragma unroll
        for (int j = 0; j < 16; j++)
            h[j] = __float2half_rn(rintf(tile[(chunk * 16 + j) * 25 + ky * 5 + kx]));
        uint4* dst = (uint4*)(wb + blob * 1024 + n * 16);
        dst[0] = ((uint4*)h)[0];
        dst[1] = ((uint4*)h)[1];
    }
}

// L4: w [192][3][5][5] -> blobs [chunk][tap9][16 rows x 16ci], n=(py*2+px)*4+co
__global__ void prep_wb4(const float* __restrict__ w) {
    int idx = blockIdx.x * blockDim.x + threadIdx.x;
    if (idx >= 12 * 9 * 16) return;
    int chunk = idx / 144;
    int r = idx % 144;
    int t = r / 16, n = r % 16;
    int dy = t / 3 - 1, dx = t % 3 - 1;
    int p = n >> 2, c = n & 3;
    int py = p >> 1, px = p & 1;
    __half h[16];
    #pragma unroll
    for (int j = 0; j < 16; j++) {
        float v = 0.f;
        if (c < 3 && (py == 0 || dy >= 0) && (px == 0 || dx >= 0)) {
            int ky = py + 2 - 2 * dy, kx = px + 2 - 2 * dx;
            v = rintf(w[((size_t)(chunk * 16 + j) * 3 + c) * 25 + ky * 5 + kx]);
        }
        h[j] = __float2half_rn(v);
    }
    uint4* dst = (uint4*)(g_wb4 + ((size_t)(chunk * 9 + t) * 16 + n) * 16);
    dst[0] = ((uint4*)h)[0];
    dst[1] = ((uint4*)h)[1];
}

// ---------------- tensor-core transposed conv: decoupled warps ----------------
// CTA: (YR x 16) sites x NTILE output-n. 256 threads = 8 warps (WM x WN).
// A smem: [(YR+2) rows][18 cols][16 ci], 48B pitch, 2-stage ring (cp.async),
//         __syncthreads only at ci-chunk boundaries.
// B smem: 6-slot ring via TMA bulk; per-slot full-mbarrier (tx) and
//         consumed-mbarrier (count 8, one arrive per warp per tap). tid0 waits
//         consumed[slot] before refilling. Warps free-run between chunk syncs.
template<int NTILE, int WM, int WN, int YR, bool LAST>
__global__ void __launch_bounds__(256, 2) conv_mma(
    const __half* __restrict__ inA, void* __restrict__ outp,
    const __half* __restrict__ Wt, const float* __restrict__ bq,
    const float* __restrict__ mul,
    int CIN, int COUT, int H, int W, int stage)
{
    constexpr int MI = YR / WM;
    constexpr int NI = NTILE / (8 * WN);
    constexpr int NPAIR = NI / 2;
    constexpr int NSITES = (YR + 2) * 18;
    constexpr int ASTG = NSITES * 48;
    constexpr int BSTG = NTILE * 32;
    __shared__ __align__(16) char smem[2 * ASTG + 6 * BSTG];
    __shared__ __align__(8) unsigned long long mbarF[6];
    __shared__ __align__(8) unsigned long long mbarC[6];

    const int tid = threadIdx.x;
    const int lane = tid & 31, wid = tid >> 5;
    const int warp_m = wid % WM, warp_n = wid / WM;
    const int x0 = blockIdx.x * 16, y0 = blockIdx.y * YR;
    int py, px, co0;
    if (LAST) { py = 0; px = 0; co0 = 0; }
    else { py = blockIdx.z & 1; px = (blockIdx.z >> 1) & 1; co0 = (blockIdx.z >> 2) * 64; }

    // A tap offsets
    int ntaps, tAoff[9];
    if (LAST) {
        ntaps = 9;
        #pragma unroll
        for (int t = 0; t < 9; t++) tAoff[t] = ((t / 3) * 18 + (t % 3)) * 48;
    } else {
        ntaps = 0;
        for (int dy = (py ? 0 : -1); dy <= 1; dy++)
            for (int dx = (px ? 0 : -1); dx <= 1; dx++)
                tAoff[ntaps++] = ((dy + 1) * 18 + (dx + 1)) * 48;
    }
    const int nchunks = CIN >> 4;
    const int niter = nchunks * ntaps;
    const int zbase = (LAST ? 0 : blockIdx.z) * nchunks;

    const u32 smem_u = (u32)__cvta_generic_to_shared(smem);
    const u32 Abase = smem_u;
    const u32 Bbase = smem_u + 2 * ASTG;
    const u32 mbF = (u32)__cvta_generic_to_shared(mbarF);
    const u32 mbC = (u32)__cvta_generic_to_shared(mbarC);

    auto loadA = [&](int chunk, int slot) {
        const int ci0 = chunk << 4;
        #pragma unroll
        for (int k = 0; k < (NSITES * 2 + 255) / 256; k++) {
            int idx = tid + k * 256;
            if (idx < NSITES * 2) {
                int site = idx >> 1, seg = idx & 1;
                int r = site / 18, c = site % 18;
                int gy = y0 - 1 + r, gx = x0 - 1 + c;
                bool ok = (unsigned)gy < (unsigned)H && (unsigned)gx < (unsigned)W;
                const __half* src = ok ? (inA + ((size_t)(gy * W + gx) * CIN + ci0 + seg * 8)) : inA;
                u32 dst = Abase + slot * ASTG + site * 48 + seg * 16;
                CPASYNC(dst, src, ok ? 16 : 0);
            }
        }
    };
    auto issueB = [&](int g) {                 // stage g -> slot g%6
        u32 mb = mbF + (g % 6) * 8;
        MBAR_EXPECT_TX(mb, BSTG);
        const __half* src = Wt + ((size_t)(zbase + g / ntaps) * 9 + g % ntaps) * (NTILE * 16);
        TMA_BULK(Bbase + (g % 6) * BSTG, src, BSTG, mb);
    };

    // init + prologue
    if (tid == 0) {
        #pragma unroll
        for (int s = 0; s < 6; s++) { MBAR_INIT(mbF + s * 8, 1); MBAR_INIT(mbC + s * 8, 8); }
    }
    loadA(0, 0); CPCOMMIT();
    __syncthreads();                           // init visible before TMA arrives
    if (tid == 0)
        for (int g = 0; g < 4; g++) issueB(g);

    float acc[MI][NI][4];
    #pragma unroll
    for (int mi = 0; mi < MI; mi++)
        #pragma unroll
        for (int ni = 0; ni < NI; ni++)
            #pragma unroll
            for (int k = 0; k < 4; k++) acc[mi][ni][k] = 0.f;

    const int la = lane & 7, ms = lane >> 3;
    const u32 aoff_lane = (u32)((la + ((ms & 1) << 3)) * 48 + ((ms >> 1) << 4));
    const int rb = la + ((lane >> 4) << 3);
    const u32 boff_lane = (u32)(rb * 32 + (((lane >> 3) & 1) << 4));

    auto compute = [&](int tap, int chunk, int slot) {
        const u32 Astage = Abase + (chunk & 1) * ASTG + tAoff[tap] + aoff_lane;
        const u32 Bstage = Bbase + slot * BSTG + warp_n * (NI * 8 * 32) + boff_lane;
        u32 a[MI][4], b[NPAIR][4];
        #pragma unroll
        for (int mi = 0; mi < MI; mi++) {
            int ylocal = warp_m * MI + mi;
            LDSM4(a[mi][0], a[mi][1], a[mi][2], a[mi][3], Astage + ylocal * (18 * 48));
        }
        #pragma unroll
        for (int p2 = 0; p2 < NPAIR; p2++)
            LDSM4(b[p2][0], b[p2][1], b[p2][2], b[p2][3], Bstage + p2 * (16 * 32));
        #pragma unroll
        for (int mi = 0; mi < MI; mi++)
            #pragma unroll
            for (int ni = 0; ni < NI; ni++)
                MMA16816(acc[mi][ni][0], acc[mi][ni][1], acc[mi][ni][2], acc[mi][ni][3],
                         a[mi][0], a[mi][1], a[mi][2], a[mi][3],
                         b[ni >> 1][(ni & 1) * 2], b[ni >> 1][(ni & 1) * 2 + 1]);
    };

    int gs = 0;
    for (int chunk = 0; chunk < nchunks; chunk++) {
        CPWAIT(0);                             // own A(chunk) cp.async groups done
        __syncthreads();                       // => all threads' A(chunk) staged;
                                               //    all warps done with chunk-1
        if (chunk + 1 < nchunks) { loadA(chunk + 1, (chunk + 1) & 1); CPCOMMIT(); }

        for (int tap = 0; tap < ntaps; tap++, gs++) {
            const int sl = gs % 6;
            MBAR_WAIT(mbF + sl * 8, (gs / 6) & 1);
            compute(tap, chunk, sl);
            if (lane == 0) MBAR_ARRIVE(mbC + sl * 8);
            if (tid == 0) {
                int g2 = gs + 4;
                if (g2 < niter) {
                    if (g2 >= 6) MBAR_WAIT(mbC + (g2 % 6) * 8, ((g2 / 6) - 1) & 1);
                    issueB(g2);
                }
            }
        }
    }

    // -------- quant epilogue --------
    float addA, invA, clpv = 0.f, sclv = 0.f, addB = 0.f, invB = 0.f;
    if (!LAST) {
        addA = g_params[stage*6+0]; invA = g_params[stage*6+1];
        clpv = g_params[stage*6+2]; sclv = g_params[stage*6+3];
        addB = g_params[stage*6+4]; invB = g_params[stage*6+5];
    } else {
        addA = g_params[18]; invA = g_params[19];
    }
    const int W2 = 2 * W;

    if (!LAST) {
        __half* out = (__half*)outp;
        #pragma unroll
        for (int mi = 0; mi < MI; mi++) {
            int ylocal = warp_m * MI + mi;
            int oy = 2 * (y0 + ylocal) + py;
            #pragma unroll
            for (int ni = 0; ni < NI; ni++) {
                int co = co0 + warp_n * (NI * 8) + ni * 8 + (lane & 3) * 2;
                float b0f = bq[co], b1f = bq[co + 1];
                float m0f = mul[co], m1f = mul[co + 1];
                #pragma unroll
                for (int h = 0; h < 2; h++) {
                    int xl = (lane >> 2) + h * 8;
                    int ox = 2 * (x0 + xl) + px;
                    float v0 = acc[mi][ni][h * 2 + 0];
                    float v1 = acc[mi][ni][h * 2 + 1];
                    v0 = floorf(((v0 + b0f) * m0f + addA) * invA);
                    v0 = fminf(fmaxf(v0, 0.f), clpv);
                    v0 = floorf((v0 * sclv + addB) * invB);
                    v1 = floorf(((v1 + b1f) * m1f + addA) * invA);
                    v1 = fminf(fmaxf(v1, 0.f), clpv);
                    v1 = floorf((v1 * sclv + addB) * invB);
                    __half2 hv = __floats2half2_rn(v0, v1);
                    *(__half2*)(out + ((size_t)oy * W2 + ox) * COUT + co) = hv;
                }
            }
        }
    } else {
        float* out = (float*)outp;
        const int PLANE = W2 * 2 * H;
        #pragma unroll
        for (int mi = 0; mi < MI; mi++) {
            int ylocal = warp_m * MI + mi;
            #pragma unroll
            for (int ni = 0; ni < NI; ni++) {
                int nbase = ni * 8 + (lane & 3) * 2;
                #pragma unroll
                for (int h = 0; h < 2; h++) {
                    int xl = (lane >> 2) + h * 8;
                    #pragma unroll
                    for (int j = 0; j < 2; j++) {
                        int n = nbase + j;
                        int p = n >> 2, c = n & 3;
                        if (c < 3) {
                            int pyy = p >> 1, pxx = p & 1;
                            int oy = 2 * (y0 + ylocal) + pyy;
                            int ox = 2 * (x0 + xl) + pxx;
                            float v = acc[mi][ni][h * 2 + j];
                            v = (v + bq[c]) * mul[c];
                            v = floorf((v + addA) * invA);
                            out[(size_t)c * PLANE + (size_t)oy * W2 + ox] = v / 255.0f;
                        }
                    }
                }
            }
        }
    }
}

// ---------------- host launcher (graph-capturable: kernel launches only) -------
extern "C" void kernel_launch(void* const* d_in, const int* in_sizes, int n_in,
                              void* d_out, int out_size)
{
    const float* x     = (const float*)d_in[0];
    const float* w1    = (const float*)d_in[1];
    const float* b1    = (const float*)d_in[2];
    const float* w2    = (const float*)d_in[3];
    const float* b2    = (const float*)d_in[4];
    const float* w3    = (const float*)d_in[5];
    const float* b3    = (const float*)d_in[6];
    const float* w4    = (const float*)d_in[7];
    const float* b4    = (const float*)d_in[8];
    const float* m0    = (const float*)d_in[9];
    const float* m1    = (const float*)d_in[10];
    const float* m2    = (const float*)d_in[11];
    const float* m3    = (const float*)d_in[12];
    const float* relus = (const float*)d_in[13];
    const int*   dvds  = (const int*)d_in[14];
    const int*   bitsp = (n_in > 15) ? (const int*)d_in[15] : nullptr;

    __half *xh, *h0, *h1, *h2, *wb1, *wb2, *wb3, *wb4;
    float *b1q, *b2q, *b3q, *b4q;
    cudaGetSymbolAddress((void**)&xh,  g_xh);
    cudaGetSymbolAddress((void**)&h0,  g_h0);
    cudaGetSymbolAddress((void**)&h1,  g_h1);
    cudaGetSymbolAddress((void**)&h2,  g_h2);
    cudaGetSymbolAddress((void**)&wb1, g_wb1);
    cudaGetSymbolAddress((void**)&wb2, g_wb2);
    cudaGetSymbolAddress((void**)&wb3, g_wb3);
    cudaGetSymbolAddress((void**)&wb4, g_wb4);
    cudaGetSymbolAddress((void**)&b1q, g_b1q);
    cudaGetSymbolAddress((void**)&b2q, g_b2q);
    cudaGetSymbolAddress((void**)&b3q, g_b3q);
    cudaGetSymbolAddress((void**)&b4q, g_b4q);

    nchw2nhwc<<<(48*48*320 + 255)/256, 256>>>(x, xh, 320, 48*48);
    prep_wb3x<<<dim3(192, 3), 256>>>(w1, w2, w3);
    prep_wb4<<<(12*9*16 + 255)/256, 256>>>(w4);
    quant_scalars<<<1, 256>>>(b1, b2, b3, b4, relus, dvds, bitsp);

    // L1: 320ch 48x48 -> 192ch 96x96
    conv_mma<64,4,2,8,false><<<dim3(3, 6, 12), 256>>>(xh, h0, wb1, b1q, m0, 320, 192, 48, 48, 0);
    // L2: 192ch 96x96 -> 192ch 192x192
    conv_mma<64,4,2,16,false><<<dim3(6, 6, 12), 256>>>(h0, h1, wb2, b2q, m1, 192, 192, 96, 96, 1);
    // L3: 192ch 192x192 -> 192ch 384x384
    conv_mma<64,4,2,16,false><<<dim3(12, 12, 12), 256>>>(h1, h2, wb3, b3q, m2, 192, 192, 192, 192, 2);
    // L4: 192ch 384x384 -> 3ch 768x768, parity-folded N=16, f32 NCHW out
    conv_mma<16,8,1,16,true><<<dim3(24, 24, 1), 256>>>(h2, d_out, wb4, b4q, m3, 192, 3, 384, 384, 3);
}

// round 16
// speedup vs baseline: 1.1300x; 1.1300x over previous
#include <cuda_runtime.h>
#include <cuda_fp16.h>
#include <math.h>

typedef unsigned int u32;

// ---------------- static device scratch (allocation-free rule) ----------------
__device__ __half g_xh[48*48*320];            // L1 input NHWC fp16
__device__ __half g_h0[96*96*192];            // L1 out / L2 in
__device__ __half g_h1[192*192*192];          // L2 out / L3 in
__device__ __half g_h2[384*384*192];          // L3 out / L4 in
// B weight BLOBS: [z][chunk][tap9] x (NTILE rows x 32B), consumption order
__device__ __align__(256) __half g_wb1[12*20*9*64*16];
__device__ __align__(256) __half g_wb2[12*12*9*64*16];
__device__ __align__(256) __half g_wb3[12*12*9*64*16];
__device__ __align__(256) __half g_wb4[12*9*16*16];
__device__ float g_b1q[192];
__device__ float g_b2q[192];
__device__ float g_b3q[192];
__device__ float g_b4q[3];
__device__ float g_params[24];

// ---------------- PTX wrappers ----------------
#define CPASYNC(dst, src, sz) \
    asm volatile("cp.async.cg.shared.global [%0], [%1], 16, %2;" :: "r"(dst), "l"(src), "r"(sz))
#define CPCOMMIT() asm volatile("cp.async.commit_group;")
#define CPWAIT(n)  asm volatile("cp.async.wait_group %0;" :: "n"(n))
#define LDSM4(r0,r1,r2,r3,addr) \
    asm volatile("ldmatrix.sync.aligned.m8n8.x4.shared.b16 {%0,%1,%2,%3}, [%4];" \
        : "=r"(r0),"=r"(r1),"=r"(r2),"=r"(r3) : "r"(addr))
#define MMA16816(c0,c1,c2,c3,a0,a1,a2,a3,b0,b1) \
    asm volatile("mma.sync.aligned.m16n8k16.row.col.f32.f16.f16.f32 " \
        "{%0,%1,%2,%3}, {%4,%5,%6,%7}, {%8,%9}, {%0,%1,%2,%3};" \
        : "+f"(c0),"+f"(c1),"+f"(c2),"+f"(c3) \
        : "r"(a0),"r"(a1),"r"(a2),"r"(a3),"r"(b0),"r"(b1))
#define MBAR_INIT(mb, cnt) \
    asm volatile("mbarrier.init.shared.b64 [%0], %1;" :: "r"(mb), "r"(cnt) : "memory")
#define MBAR_EXPECT_TX(mb, bytes) \
    asm volatile("mbarrier.arrive.expect_tx.shared.b64 _, [%0], %1;" :: "r"(mb), "r"(bytes) : "memory")
#define TMA_BULK(dst, src, bytes, mb) \
    asm volatile("cp.async.bulk.shared::cluster.global.mbarrier::complete_tx::bytes [%0], [%1], %2, [%3];" \
        :: "r"(dst), "l"(src), "r"(bytes), "r"(mb) : "memory")
#define MBAR_WAIT(mb, parity) do { \
    u32 _done = 0; \
    while (!_done) { \
        asm volatile("{\n\t.reg .pred p;\n\t" \
            "mbarrier.try_wait.parity.acquire.cta.shared::cta.b64 p, [%1], %2;\n\t" \
            "selp.b32 %0, 1, 0, p;\n\t}" \
            : "=r"(_done) : "r"(mb), "r"(parity) : "memory"); \
    } \
} while(0)

// ---------------- prep kernels ----------------
// NCHW f32 -> NHWC fp16 (values are small ints: exact)
__global__ void nchw2nhwc(const float* __restrict__ src, __half* __restrict__ dst,
                          int C, int HW) {
    int idx = blockIdx.x * blockDim.x + threadIdx.x;
    if (idx >= C * HW) return;
    int s = idx / C, c = idx % C;
    dst[idx] = __float2half_rn(src[c * HW + s]);
}

// Layers 1-3 blobs + (block 0 of layer 0 also does scalars/biases).
__global__ void prep_wb3x(const float* __restrict__ w1, const float* __restrict__ w2,
                          const float* __restrict__ w3,
                          const float* __restrict__ b1, const float* __restrict__ b2,
                          const float* __restrict__ b3, const float* __restrict__ b4,
                          const float* __restrict__ relus, const int* __restrict__ dvds,
                          const int* __restrict__ bitsp) {
    __shared__ float tile[320 * 25];
    const int which = blockIdx.y;
    const float* w = which == 0 ? w1 : (which == 1 ? w2 : w3);
    __half* wb     = which == 0 ? g_wb1 : (which == 1 ? g_wb2 : g_wb3);
    const int CIN  = which == 0 ? 320 : 192;
    const int COUT = 192;
    const int co = blockIdx.x;
    const int tid = threadIdx.x;

    if (which == 0 && co == 0) {               // fold scalar prep into this launch
        int i = tid;
        if (i < 192) {
            g_b1q[i] = rintf(b1[i]);
            g_b2q[i] = rintf(b2[i]);
            g_b3q[i] = rintf(b3[i]);
        }
        if (i < 3) g_b4q[i] = rintf(b4[i]);
        if (i == 224) {
            float B = bitsp ? (float)(*bitsp) : 8.0f;
            float maxv = exp2f(B) - 1.0f;
            const int sks[3] = {3, 4, 3};
            for (int k = 0; k < 3; k++) {
                float dv = (float)dvds[k];
                g_params[k*6+0] = exp2f(dv - 10.0f);
                g_params[k*6+1] = exp2f(9.0f - dv);
                g_params[k*6+2] = rintf((maxv / relus[k]) * 33554432.0f);
                float sk = (float)sks[k];
                g_params[k*6+3] = floorf((relus[k] + exp2f(sk - 1.0f)) * exp2f(-sk));
                g_params[k*6+4] = exp2f(24.0f - sk);
                g_params[k*6+5] = exp2f(sk - 25.0f);
            }
            float dv3 = (float)dvds[3];
            g_params[18] = exp2f(dv3 - 9.0f);
            g_params[19] = exp2f(8.0f - dv3);
        }
    }

    for (int i = tid; i < CIN * 25; i += 256) {
        int ci = i / 25, t = i % 25;
        tile[i] = w[((size_t)ci * COUT + co) * 25 + t];
    }
    __syncthreads();
    const int nchk = CIN >> 4;
    const int n = co & 63, cog = co >> 6;
    for (int i = tid; i < 25 * nchk; i += 256) {
        int pt = i / nchk, chunk = i % nchk;
        int p, t;
        if (pt < 9)       { p = 0; t = pt; }
        else if (pt < 15) { p = 1; t = pt - 9; }
        else if (pt < 21) { p = 2; t = pt - 15; }
        else              { p = 3; t = pt - 21; }
        int py = p & 1, px = p >> 1;
        int ndx = px ? 2 : 3;
        int dy = (py ? 0 : -1) + t / ndx;
        int dx = (px ? 0 : -1) + t % ndx;
        int ky = py + 2 - 2 * dy, kx = px + 2 - 2 * dx;
        int z = cog * 4 + p;
        size_t blob = ((size_t)z * nchk + chunk) * 9 + t;
        __half h[16];
        #pragma unroll
        for (int j = 0; j < 16; j++)
            h[j] = __float2half_rn(rintf(tile[(chunk * 16 + j) * 25 + ky * 5 + kx]));
        uint4* dst = (uint4*)(wb + blob * 1024 + n * 16);
        dst[0] = ((uint4*)h)[0];
        dst[1] = ((uint4*)h)[1];
    }
}

// L4: w [192][3][5][5] -> blobs [chunk][tap9][16 rows x 16ci], n=(py*2+px)*4+co
__global__ void prep_wb4(const float* __restrict__ w) {
    int idx = blockIdx.x * blockDim.x + threadIdx.x;
    if (idx >= 12 * 9 * 16) return;
    int chunk = idx / 144;
    int r = idx % 144;
    int t = r / 16, n = r % 16;
    int dy = t / 3 - 1, dx = t % 3 - 1;
    int p = n >> 2, c = n & 3;
    int py = p >> 1, px = p & 1;
    __half h[16];
    #pragma unroll
    for (int j = 0; j < 16; j++) {
        float v = 0.f;
        if (c < 3 && (py == 0 || dy >= 0) && (px == 0 || dx >= 0)) {
            int ky = py + 2 - 2 * dy, kx = px + 2 - 2 * dx;
            v = rintf(w[((size_t)(chunk * 16 + j) * 3 + c) * 25 + ky * 5 + kx]);
        }
        h[j] = __float2half_rn(v);
    }
    uint4* dst = (uint4*)(g_wb4 + ((size_t)(chunk * 9 + t) * 16 + n) * 16);
    dst[0] = ((uint4*)h)[0];
    dst[1] = ((uint4*)h)[1];
}

// ---------------- tensor-core transposed conv: paired iterations ---------------
// CTA: (YR x 16) sites x NTILE output-n. 256 threads = 8 warps (WM x WN).
// A smem: [(YR+2) rows][18 cols][16 ci], 48B pitch, 2-stage ring (cp.async).
// B smem: 8 slots of NTILE x 32B packed blobs via TMA bulk, slot = i mod 8,
// phase = (i/8)&1, prefetch +6. TWO taps consumed per __syncthreads; the
// second stage's wait is issued between the two compute halves.
template<int NTILE, int WM, int WN, int YR, bool LAST>
__global__ void __launch_bounds__(256, 2) conv_mma(
    const __half* __restrict__ inA, void* __restrict__ outp,
    const __half* __restrict__ Wt, const float* __restrict__ bq,
    const float* __restrict__ mul,
    int CIN, int COUT, int H, int W, int stage)
{
    constexpr int MI = YR / WM;
    constexpr int NI = NTILE / (8 * WN);
    constexpr int NPAIR = NI / 2;
    constexpr int NSITES = (YR + 2) * 18;
    constexpr int ASTG = NSITES * 48;
    constexpr int BSTG = NTILE * 32;
    __shared__ __align__(16) char smem[2 * ASTG + 8 * BSTG];
    __shared__ __align__(8) unsigned long long mbarB[8];

    const int tid = threadIdx.x;
    const int lane = tid & 31, wid = tid >> 5;
    const int warp_m = wid % WM, warp_n = wid / WM;
    const int x0 = blockIdx.x * 16, y0 = blockIdx.y * YR;
    int py, px, co0;
    if (LAST) { py = 0; px = 0; co0 = 0; }
    else { py = blockIdx.z & 1; px = (blockIdx.z >> 1) & 1; co0 = (blockIdx.z >> 2) * 64; }

    // A tap offsets
    int ntaps, tAoff[9];
    if (LAST) {
        ntaps = 9;
        #pragma unroll
        for (int t = 0; t < 9; t++) tAoff[t] = ((t / 3) * 18 + (t % 3)) * 48;
    } else {
        ntaps = 0;
        for (int dy = (py ? 0 : -1); dy <= 1; dy++)
            for (int dx = (px ? 0 : -1); dx <= 1; dx++)
                tAoff[ntaps++] = ((dy + 1) * 18 + (dx + 1)) * 48;
    }
    const int nchunks = CIN >> 4;
    const int niter = nchunks * ntaps;          // even for all configs used
    const int zbase = (LAST ? 0 : blockIdx.z) * nchunks;

    const u32 smem_u = (u32)__cvta_generic_to_shared(smem);
    const u32 Abase = smem_u;
    const u32 Bbase = smem_u + 2 * ASTG;
    const u32 mbar_u = (u32)__cvta_generic_to_shared(mbarB);

    auto loadA = [&](int chunk, int slot) {
        const int ci0 = chunk << 4;
        #pragma unroll
        for (int k = 0; k < (NSITES * 2 + 255) / 256; k++) {
            int idx = tid + k * 256;
            if (idx < NSITES * 2) {
                int site = idx >> 1, seg = idx & 1;
                int r = site / 18, c = site % 18;
                int gy = y0 - 1 + r, gx = x0 - 1 + c;
                bool ok = (unsigned)gy < (unsigned)H && (unsigned)gx < (unsigned)W;
                const __half* src = ok ? (inA + ((size_t)(gy * W + gx) * CIN + ci0 + seg * 8)) : inA;
                u32 dst = Abase + slot * ASTG + site * 48 + seg * 16;
                CPASYNC(dst, src, ok ? 16 : 0);
            }
        }
    };
    auto issueB = [&](int tap, int chunk, int slot) {
        if (tid == 0) {
            u32 mb = mbar_u + slot * 8;
            MBAR_EXPECT_TX(mb, BSTG);
            const __half* src = Wt + ((size_t)(zbase + chunk) * 9 + tap) * (NTILE * 16);
            TMA_BULK(Bbase + slot * BSTG, src, BSTG, mb);
        }
    };

    // init + prologue: A(0) + B stages 0..5 (slots 0..5 of 8)
    if (tid == 0) {
        #pragma unroll
        for (int s = 0; s < 8; s++) MBAR_INIT(mbar_u + s * 8, 1);
    }
    loadA(0, 0); CPCOMMIT();
    __syncthreads();                           // init visible before TMA arrives
    int pf_tap = 0, pf_chunk = 0;
    for (int k = 0; k < 6; k++) {
        if (k < niter) {
            issueB(pf_tap, pf_chunk, k);
            if (++pf_tap == ntaps) { pf_tap = 0; pf_chunk++; }
        }
    }

    float acc[MI][NI][4];
    #pragma unroll
    for (int mi = 0; mi < MI; mi++)
        #pragma unroll
        for (int ni = 0; ni < NI; ni++)
            #pragma unroll
            for (int k = 0; k < 4; k++) acc[mi][ni][k] = 0.f;

    const int la = lane & 7, ms = lane >> 3;
    const u32 aoff_lane = (u32)((la + ((ms & 1) << 3)) * 48 + ((ms >> 1) << 4));
    const int rb = la + ((lane >> 4) << 3);
    const u32 boff_lane = (u32)(rb * 32 + (((lane >> 3) & 1) << 4));

    auto compute = [&](int tap, int chunk, int slot) {
        const u32 Astage = Abase + (chunk & 1) * ASTG + tAoff[tap] + aoff_lane;
        const u32 Bstage = Bbase + slot * BSTG + warp_n * (NI * 8 * 32) + boff_lane;
        u32 a[MI][4], b[NPAIR][4];
        #pragma unroll
        for (int mi = 0; mi < MI; mi++) {
            int ylocal = warp_m * MI + mi;
            LDSM4(a[mi][0], a[mi][1], a[mi][2], a[mi][3], Astage + ylocal * (18 * 48));
        }
        #pragma unroll
        for (int p2 = 0; p2 < NPAIR; p2++)
            LDSM4(b[p2][0], b[p2][1], b[p2][2], b[p2][3], Bstage + p2 * (16 * 32));
        #pragma unroll
        for (int mi = 0; mi < MI; mi++)
            #pragma unroll
            for (int ni = 0; ni < NI; ni++)
                MMA16816(acc[mi][ni][0], acc[mi][ni][1], acc[mi][ni][2], acc[mi][ni][3],
                         a[mi][0], a[mi][1], a[mi][2], a[mi][3],
                         b[ni >> 1][(ni & 1) * 2], b[ni >> 1][(ni & 1) * 2 + 1]);
    };

    int cur_tap = 0, cur_chunk = 0;
    for (int i = 0; i < niter; i += 2) {
        int tap1 = cur_tap + 1, chunk1 = cur_chunk;
        if (tap1 == ntaps) { tap1 = 0; chunk1++; }

        // A residency for any chunk whose first tap is in this pair.
        if (cur_tap == 0 || tap1 == 0) CPWAIT(0);

        const int s0 = i % 8, s1 = (i + 1) % 8;
        MBAR_WAIT(mbar_u + s0 * 8, (i / 8) & 1);
        __syncthreads();                       // slots (i+6)%8,(i+7)%8 fully consumed

        if (i + 6 < niter) {
            issueB(pf_tap, pf_chunk, (i + 6) % 8);
            if (++pf_tap == ntaps) { pf_tap = 0; pf_chunk++; }
        }
        if (i + 7 < niter) {
            issueB(pf_tap, pf_chunk, (i + 7) % 8);
            if (++pf_tap == ntaps) { pf_tap = 0; pf_chunk++; }
        }
        {
            int sc = (cur_tap == 0) ? cur_chunk : ((tap1 == 0) ? chunk1 : -1);
            if (sc >= 0 && sc + 1 < nchunks) { loadA(sc + 1, (sc + 1) & 1); CPCOMMIT(); }
        }

        compute(cur_tap, cur_chunk, s0);
        MBAR_WAIT(mbar_u + s1 * 8, ((i + 1) / 8) & 1);
        compute(tap1, chunk1, s1);

        cur_tap = tap1 + 1; cur_chunk = chunk1;
        if (cur_tap == ntaps) { cur_tap = 0; cur_chunk++; }
    }

    // -------- quant epilogue --------
    float addA, invA, clpv = 0.f, sclv = 0.f, addB = 0.f, invB = 0.f;
    if (!LAST) {
        addA = g_params[stage*6+0]; invA = g_params[stage*6+1];
        clpv = g_params[stage*6+2]; sclv = g_params[stage*6+3];
        addB = g_params[stage*6+4]; invB = g_params[stage*6+5];
    } else {
        addA = g_params[18]; invA = g_params[19];
    }
    const int W2 = 2 * W;

    if (!LAST) {
        __half* out = (__half*)outp;
        #pragma unroll
        for (int mi = 0; mi < MI; mi++) {
            int ylocal = warp_m * MI + mi;
            int oy = 2 * (y0 + ylocal) + py;
            #pragma unroll
            for (int ni = 0; ni < NI; ni++) {
                int co = co0 + warp_n * (NI * 8) + ni * 8 + (lane & 3) * 2;
                float b0f = bq[co], b1f = bq[co + 1];
                float m0f = mul[co], m1f = mul[co + 1];
                #pragma unroll
                for (int h = 0; h < 2; h++) {
                    int xl = (lane >> 2) + h * 8;
                    int ox = 2 * (x0 + xl) + px;
                    float v0 = acc[mi][ni][h * 2 + 0];
                    float v1 = acc[mi][ni][h * 2 + 1];
                    v0 = floorf(((v0 + b0f) * m0f + addA) * invA);
                    v0 = fminf(fmaxf(v0, 0.f), clpv);
                    v0 = floorf((v0 * sclv + addB) * invB);
                    v1 = floorf(((v1 + b1f) * m1f + addA) * invA);
                    v1 = fminf(fmaxf(v1, 0.f), clpv);
                    v1 = floorf((v1 * sclv + addB) * invB);
                    __half2 hv = __floats2half2_rn(v0, v1);
                    *(__half2*)(out + ((size_t)oy * W2 + ox) * COUT + co) = hv;
                }
            }
        }
    } else {
        float* out = (float*)outp;
        const int PLANE = W2 * 2 * H;
        #pragma unroll
        for (int mi = 0; mi < MI; mi++) {
            int ylocal = warp_m * MI + mi;
            #pragma unroll
            for (int ni = 0; ni < NI; ni++) {
                int nbase = ni * 8 + (lane & 3) * 2;
                #pragma unroll
                for (int h = 0; h < 2; h++) {
                    int xl = (lane >> 2) + h * 8;
                    #pragma unroll
                    for (int j = 0; j < 2; j++) {
                        int n = nbase + j;
                        int p = n >> 2, c = n & 3;
                        if (c < 3) {
                            int pyy = p >> 1, pxx = p & 1;
                            int oy = 2 * (y0 + ylocal) + pyy;
                            int ox = 2 * (x0 + xl) + pxx;
                            float v = acc[mi][ni][h * 2 + j];
                            v = (v + bq[c]) * mul[c];
                            v = floorf((v + addA) * invA);
                            out[(size_t)c * PLANE + (size_t)oy * W2 + ox] = v / 255.0f;
                        }
                    }
                }
            }
        }
    }
}

// ---------------- host launcher (graph-capturable: kernel launches only) -------
extern "C" void kernel_launch(void* const* d_in, const int* in_sizes, int n_in,
                              void* d_out, int out_size)
{
    const float* x     = (const float*)d_in[0];
    const float* w1    = (const float*)d_in[1];
    const float* b1    = (const float*)d_in[2];
    const float* w2    = (const float*)d_in[3];
    const float* b2    = (const float*)d_in[4];
    const float* w3    = (const float*)d_in[5];
    const float* b3    = (const float*)d_in[6];
    const float* w4    = (const float*)d_in[7];
    const float* b4    = (const float*)d_in[8];
    const float* m0    = (const float*)d_in[9];
    const float* m1    = (const float*)d_in[10];
    const float* m2    = (const float*)d_in[11];
    const float* m3    = (const float*)d_in[12];
    const float* relus = (const float*)d_in[13];
    const int*   dvds  = (const int*)d_in[14];
    const int*   bitsp = (n_in > 15) ? (const int*)d_in[15] : nullptr;

    __half *xh, *h0, *h1, *h2, *wb1, *wb2, *wb3, *wb4;
    float *b1q, *b2q, *b3q, *b4q;
    cudaGetSymbolAddress((void**)&xh,  g_xh);
    cudaGetSymbolAddress((void**)&h0,  g_h0);
    cudaGetSymbolAddress((void**)&h1,  g_h1);
    cudaGetSymbolAddress((void**)&h2,  g_h2);
    cudaGetSymbolAddress((void**)&wb1, g_wb1);
    cudaGetSymbolAddress((void**)&wb2, g_wb2);
    cudaGetSymbolAddress((void**)&wb3, g_wb3);
    cudaGetSymbolAddress((void**)&wb4, g_wb4);
    cudaGetSymbolAddress((void**)&b1q, g_b1q);
    cudaGetSymbolAddress((void**)&b2q, g_b2q);
    cudaGetSymbolAddress((void**)&b3q, g_b3q);
    cudaGetSymbolAddress((void**)&b4q, g_b4q);

    nchw2nhwc<<<(48*48*320 + 255)/256, 256>>>(x, xh, 320, 48*48);
    prep_wb3x<<<dim3(192, 3), 256>>>(w1, w2, w3, b1, b2, b3, b4, relus, dvds, bitsp);
    prep_wb4<<<(12*9*16 + 255)/256, 256>>>(w4);

    // L1: 320ch 48x48 -> 192ch 96x96
    conv_mma<64,4,2,8,false><<<dim3(3, 6, 12), 256>>>(xh, h0, wb1, b1q, m0, 320, 192, 48, 48, 0);
    // L2: 192ch 96x96 -> 192ch 192x192
    conv_mma<64,4,2,16,false><<<dim3(6, 6, 12), 256>>>(h0, h1, wb2, b2q, m1, 192, 192, 96, 96, 1);
    // L3: 192ch 192x192 -> 192ch 384x384
    conv_mma<64,4,2,16,false><<<dim3(12, 12, 12), 256>>>(h1, h2, wb3, b3q, m2, 192, 192, 192, 192, 2);
    // L4: 192ch 384x384 -> 3ch 768x768, parity-folded N=16, f32 NCHW out, YR=32
    conv_mma<16,8,1,32,true><<<dim3(24, 12, 1), 256>>>(h2, d_out, wb4, b4q, m3, 192, 3, 384, 384, 3);
}